// round 1
// baseline (speedup 1.0000x reference)
#include <cuda_runtime.h>
#include <cuda_bf16.h>
#include <cstdint>

// ---------------------------------------------------------------------------
// GNNRepresentationNetwork: B=16, C=16, H=W=64 (N=4096), D_E=64, D_H=128, D_R=256
//
// Layout choice: all activations are feature-major [b][d][n] (n fastest).
//   - obs is already [b][c][n]
//   - stencil (grid adjacency) is contiguous along n
//   - mean over n is a contiguous reduction
//   - GEMM computes out[d][n] = sum_k W[k][d] * in[k][n]  (i.e. C^T = W^T A)
//
// GCN layer identity (exact): relu(A(hW + b)) = relu((A h)W + s_n * b),
//   s_n = deg_n / (deg_n + 1e-6), since A is row-normalized by (deg + 1e-6).
// ---------------------------------------------------------------------------

#define B_  16
#define N_  4096   // 64*64
#define W_  64

// Scratch (device globals: allocation-free rule)
__device__ float g_bufA[B_ * 128 * N_];   // 33.5 MB
__device__ float g_bufB[B_ * 128 * N_];   // 33.5 MB
__device__ float g_vec[B_ * 128];         // graph readout vector

// ---------------------------------------------------------------------------
// GEMM: out[b][d][n] = relu( sum_k A[b][k][n] * Wt[k][d] + s_n * bias[d] )
// A batch stride = K*N_, out batch stride = D*N_.
// Block: 128 n-values x D d-values. 256 threads: tx(0..31) -> 4 consecutive n,
// ty(0..7) -> TN = D/8 consecutive d. Register tile TN x 4.
// ---------------------------------------------------------------------------
template <int K, int D, bool SCALED_BIAS>
__global__ void __launch_bounds__(256)
gemm_relu_kernel(const float* __restrict__ A, const float* __restrict__ Wt,
                 const float* __restrict__ bias, float* __restrict__ out)
{
    constexpr int KC = 16;
    constexpr int TN = D / 8;

    __shared__ float As[KC][128];
    __shared__ float Ws[KC][D];

    const int tid = threadIdx.x;
    const int tx  = tid & 31;   // n-group
    const int ty  = tid >> 5;   // d-group

    const int m0 = blockIdx.x * 128;       // global row base (b*N_ + n0)
    const int b  = m0 >> 12;               // / N_
    const int n0 = m0 & (N_ - 1);
    const float* Ab = A + (size_t)b * K * N_ + n0;

    float acc[TN][4];
#pragma unroll
    for (int i = 0; i < TN; i++)
#pragma unroll
        for (int j = 0; j < 4; j++) acc[i][j] = 0.f;

    for (int kc = 0; kc < K; kc += KC) {
        // Load As: 16 rows x 128 floats (512 float4), 2 per thread, coalesced.
        {
            const int r = tid >> 5;    // 0..7
            const int c = tid & 31;    // float4 index within row
            const float4* s0 = reinterpret_cast<const float4*>(Ab + (size_t)(kc + r) * N_) + c;
            const float4* s1 = reinterpret_cast<const float4*>(Ab + (size_t)(kc + r + 8) * N_) + c;
            *reinterpret_cast<float4*>(&As[r][c * 4])     = *s0;
            *reinterpret_cast<float4*>(&As[r + 8][c * 4]) = *s1;
        }
        // Load Ws: 16 x D floats
        {
            constexpr int F4 = D / 4;                  // float4 per row
#pragma unroll
            for (int t = tid; t < 16 * F4; t += 256) {
                const int r = t / F4, c = t % F4;
                *reinterpret_cast<float4*>(&Ws[r][c * 4]) =
                    *(reinterpret_cast<const float4*>(Wt + (size_t)(kc + r) * D) + c);
            }
        }
        __syncthreads();

#pragma unroll
        for (int k = 0; k < KC; k++) {
            const float4 a = *reinterpret_cast<const float4*>(&As[k][tx * 4]);
#pragma unroll
            for (int dd = 0; dd < TN; dd += 4) {
                const float4 w = *reinterpret_cast<const float4*>(&Ws[k][ty * TN + dd]);
                acc[dd + 0][0] += w.x * a.x; acc[dd + 0][1] += w.x * a.y;
                acc[dd + 0][2] += w.x * a.z; acc[dd + 0][3] += w.x * a.w;
                acc[dd + 1][0] += w.y * a.x; acc[dd + 1][1] += w.y * a.y;
                acc[dd + 1][2] += w.y * a.z; acc[dd + 1][3] += w.y * a.w;
                acc[dd + 2][0] += w.z * a.x; acc[dd + 2][1] += w.z * a.y;
                acc[dd + 2][2] += w.z * a.z; acc[dd + 2][3] += w.z * a.w;
                acc[dd + 3][0] += w.w * a.x; acc[dd + 3][1] += w.w * a.y;
                acc[dd + 3][2] += w.w * a.z; acc[dd + 3][3] += w.w * a.w;
            }
        }
        __syncthreads();
    }

    // Epilogue: bias (optionally scaled by deg/(deg+eps)) + relu, float4 store.
    float s[4];
#pragma unroll
    for (int j = 0; j < 4; j++) {
        if (SCALED_BIAS) {
            const int nn = n0 + tx * 4 + j;
            const int gi = nn >> 6, gj = nn & 63;
            const int deg = (gi > 0) + (gi < 63) + (gj > 0) + (gj < 63);
            const float fd = (float)deg;
            s[j] = fd / (fd + 1e-6f);
        } else {
            s[j] = 1.0f;
        }
    }

    float* outb = out + (size_t)b * D * N_ + n0 + tx * 4;
#pragma unroll
    for (int dd = 0; dd < TN; dd++) {
        const int d = ty * TN + dd;
        const float bv = __ldg(&bias[d]);
        float4 o;
        o.x = fmaxf(fmaf(s[0], bv, acc[dd][0]), 0.f);
        o.y = fmaxf(fmaf(s[1], bv, acc[dd][1]), 0.f);
        o.z = fmaxf(fmaf(s[2], bv, acc[dd][2]), 0.f);
        o.w = fmaxf(fmaf(s[3], bv, acc[dd][3]), 0.f);
        *reinterpret_cast<float4*>(outb + (size_t)d * N_) = o;
    }
}

// ---------------------------------------------------------------------------
// Stencil: out[p][n] = (sum of 4-neighbors of in[p][n]) / (deg + 1e-6)
// p indexes (b, d) planes (contiguous). Grid-stride one thread per element.
// ---------------------------------------------------------------------------
__global__ void __launch_bounds__(256)
stencil_kernel(const float* __restrict__ in, float* __restrict__ out)
{
    const int idx = blockIdx.x * 256 + threadIdx.x;
    const int n = idx & (N_ - 1);
    const int i = n >> 6, j = n & 63;
    const float* p = in + (idx - n);

    float sum = 0.f;
    int deg = 0;
    if (i > 0)  { sum += p[n - W_]; deg++; }
    if (i < 63) { sum += p[n + W_]; deg++; }
    if (j > 0)  { sum += p[n - 1];  deg++; }
    if (j < 63) { sum += p[n + 1];  deg++; }

    // 1/(deg+1e-6) for deg in {2,3,4}
    const float r = (deg == 4) ? 0.2499999375f
                  : (deg == 3) ? 0.3333332222f
                               : 0.4999997500f;
    out[idx] = sum * r;
}

// ---------------------------------------------------------------------------
// Mean over n: g[p] = mean_n in[p][n], one block per (b,d) plane.
// ---------------------------------------------------------------------------
__global__ void __launch_bounds__(256)
mean_kernel(const float* __restrict__ in, float* __restrict__ g)
{
    const int p = blockIdx.x;
    const float* base = in + (size_t)p * N_;
    float s = 0.f;
#pragma unroll 4
    for (int i = threadIdx.x; i < N_; i += 256) s += base[i];

    __shared__ float red[256];
    red[threadIdx.x] = s;
    __syncthreads();
#pragma unroll
    for (int off = 128; off > 0; off >>= 1) {
        if (threadIdx.x < off) red[threadIdx.x] += red[threadIdx.x + off];
        __syncthreads();
    }
    if (threadIdx.x == 0) g[p] = red[0] * (1.0f / (float)N_);
}

// ---------------------------------------------------------------------------
// Readout: out[b] = relu( relu(g[b] @ r1w + r1b) @ r2w + r2b ),  (128->256->256)
// One block per batch element, 256 threads (one per output column).
// ---------------------------------------------------------------------------
__global__ void __launch_bounds__(256)
readout_kernel(const float* __restrict__ g,
               const float* __restrict__ r1w, const float* __restrict__ r1b,
               const float* __restrict__ r2w, const float* __restrict__ r2b,
               float* __restrict__ out)
{
    __shared__ float gs[128];
    __shared__ float ts[256];
    const int b = blockIdx.x;
    const int t = threadIdx.x;

    if (t < 128) gs[t] = g[b * 128 + t];
    __syncthreads();

    float acc = r1b[t];
#pragma unroll 8
    for (int k = 0; k < 128; k++) acc = fmaf(gs[k], r1w[k * 256 + t], acc);
    ts[t] = fmaxf(acc, 0.f);
    __syncthreads();

    float acc2 = r2b[t];
#pragma unroll 8
    for (int k = 0; k < 256; k++) acc2 = fmaf(ts[k], r2w[k * 256 + t], acc2);
    out[b * 256 + t] = fmaxf(acc2, 0.f);
}

// ---------------------------------------------------------------------------
// Launch
// ---------------------------------------------------------------------------
extern "C" void kernel_launch(void* const* d_in, const int* in_sizes, int n_in,
                              void* d_out, int out_size)
{
    const float* obs  = (const float*)d_in[0];
    const float* e1_w = (const float*)d_in[1];
    const float* e1_b = (const float*)d_in[2];
    const float* e2_w = (const float*)d_in[3];
    const float* e2_b = (const float*)d_in[4];
    const float* g1_w = (const float*)d_in[5];
    const float* g1_b = (const float*)d_in[6];
    const float* g2_w = (const float*)d_in[7];
    const float* g2_b = (const float*)d_in[8];
    const float* g3_w = (const float*)d_in[9];
    const float* g3_b = (const float*)d_in[10];
    const float* r1_w = (const float*)d_in[11];
    const float* r1_b = (const float*)d_in[12];
    const float* r2_w = (const float*)d_in[13];
    const float* r2_b = (const float*)d_in[14];
    float* out = (float*)d_out;

    float *bufA, *bufB, *vec;
    cudaGetSymbolAddress((void**)&bufA, g_bufA);
    cudaGetSymbolAddress((void**)&bufB, g_bufB);
    cudaGetSymbolAddress((void**)&vec,  g_vec);

    const int GB = (B_ * N_) / 128;   // 512 GEMM blocks

    // Embed: obs [b][16][n] -> relu MLP (16->64->64)
    gemm_relu_kernel<16, 64, false><<<GB, 256>>>(obs,  e1_w, e1_b, bufA);
    gemm_relu_kernel<64, 64, false><<<GB, 256>>>(bufA, e2_w, e2_b, bufB);

    // GCN layer 1: aggregate(64) then 64->128 GEMM with scaled bias + relu
    stencil_kernel<<<(B_ * 64 * N_) / 256, 256>>>(bufB, bufA);
    gemm_relu_kernel<64, 128, true><<<GB, 256>>>(bufA, g1_w, g1_b, bufB);

    // GCN layer 2
    stencil_kernel<<<(B_ * 128 * N_) / 256, 256>>>(bufB, bufA);
    gemm_relu_kernel<128, 128, true><<<GB, 256>>>(bufA, g2_w, g2_b, bufB);

    // GCN layer 3
    stencil_kernel<<<(B_ * 128 * N_) / 256, 256>>>(bufB, bufA);
    gemm_relu_kernel<128, 128, true><<<GB, 256>>>(bufA, g3_w, g3_b, bufB);

    // Graph mean readout + output MLP
    mean_kernel<<<B_ * 128, 256>>>(bufB, vec);
    readout_kernel<<<B_, 256>>>(vec, r1_w, r1_b, r2_w, r2_b, out);
}

// round 2
// speedup vs baseline: 1.0011x; 1.0011x over previous
#include <cuda_runtime.h>
#include <cuda_bf16.h>
#include <cstdint>

// ---------------------------------------------------------------------------
// GNNRepresentationNetwork  B=16, C=16, N=4096 (64x64), D_E=64, D_H=128, D_R=256
// Feature-major activations [b][d][n].  5 kernels:
//   1) embed:   obs -> relu MLP(16->64->64), both layers fused (h1 in smem)
//   2) gcn<64>: stencil fused into GEMM prologue, FFMA2 math
//   3) gcn<128>
//   4) gcn<128, MEAN>: no output store; per-block partial sums (deterministic)
//   5) readout: partial-sum reduce + 2-layer MLP
// GCN identity (exact): relu(A(hW+b)) = relu((A h)W + s_n b), s_n = deg/(deg+1e-6)
// ---------------------------------------------------------------------------

#define B_  16
#define N_  4096

typedef unsigned long long u64;

__device__ float g_bufA[B_ * 128 * N_];
__device__ float g_bufB[B_ * 128 * N_];
__device__ float g_part[B_ * 32 * 128];

__device__ __forceinline__ void fma2(u64& d, u64 a, u64 b) {
    asm("fma.rn.f32x2 %0, %1, %2, %0;" : "+l"(d) : "l"(a), "l"(b));
}
__device__ __forceinline__ u64 pack2(float lo, float hi) {
    u64 r; asm("mov.b64 %0, {%1, %2};" : "=l"(r) : "f"(lo), "f"(hi)); return r;
}
__device__ __forceinline__ float2 unpack2(u64 v) {
    float2 f; asm("mov.b64 {%0, %1}, %2;" : "=f"(f.x), "=f"(f.y) : "l"(v)); return f;
}
__device__ __forceinline__ float recip_deg(int deg) {
    // 1/(deg + 1e-6) for deg in {2,3,4}
    return deg == 4 ? 0.2499999375f : (deg == 3 ? 0.3333332222f : 0.4999997500f);
}

// ---------------------------------------------------------------------------
// Fused embed MLP: out[b][d][n] = relu(relu(x W1 + b1) W2 + b2), d in [0,64)
// Block = 128 n. smem: Xs[16][128] (reused as W2 tile), W1d[16][128], Hs[64][128]
// ---------------------------------------------------------------------------
__global__ void __launch_bounds__(256)
embed_kernel(const float* __restrict__ obs,
             const float* __restrict__ w1, const float* __restrict__ b1,
             const float* __restrict__ w2, const float* __restrict__ b2,
             float* __restrict__ out)
{
    __shared__ __align__(16) float sm[12288];   // 48 KB
    float* Xs  = sm;           // [16][128]; later: W2 tile (dup)
    float* W1d = sm + 2048;    // [16][128]  (64 d duplicated)
    float* Hs  = sm + 4096;    // [64][128]

    const int tid = threadIdx.x, tx = tid & 31, ty = tid >> 5;
    const int m0 = blockIdx.x * 128;
    const int b  = m0 >> 12, n0 = m0 & (N_ - 1);
    const float* xb = obs + (size_t)b * 16 * N_ + n0;

    // Stage obs tile: 16 rows x 128 floats (512 float4, 2 per thread)
    {
        const int i0 = tid, i1 = tid + 256;
        *reinterpret_cast<float4*>(&Xs[(i0 >> 5) * 128 + (i0 & 31) * 4]) =
            *(reinterpret_cast<const float4*>(xb + (size_t)(i0 >> 5) * N_) + (i0 & 31));
        *reinterpret_cast<float4*>(&Xs[(i1 >> 5) * 128 + (i1 & 31) * 4]) =
            *(reinterpret_cast<const float4*>(xb + (size_t)(i1 >> 5) * N_) + (i1 & 31));
    }
    // W1 duplicated {w,w}: 16x64 entries, 4 per thread
#pragma unroll
    for (int t = tid; t < 16 * 64; t += 256) {
        const int r = t >> 6, d = t & 63;
        const float w = w1[r * 64 + d];
        W1d[r * 128 + 2 * d] = w; W1d[r * 128 + 2 * d + 1] = w;
    }
    __syncthreads();

    // Layer 1: thread computes d = ty*8+dd (8 d) x n = n0+tx*4 (4 n, 2 pairs)
    u64 acc[8][2];
#pragma unroll
    for (int dd = 0; dd < 8; dd++) {
        const float bv = b1[ty * 8 + dd];
        acc[dd][0] = acc[dd][1] = pack2(bv, bv);
    }
#pragma unroll
    for (int k = 0; k < 16; k++) {
        const ulonglong2 a2 = *reinterpret_cast<const ulonglong2*>(&Xs[k * 128 + tx * 4]);
#pragma unroll
        for (int dd = 0; dd < 8; dd += 2) {
            const ulonglong2 w2v = *reinterpret_cast<const ulonglong2*>(&W1d[k * 128 + (ty * 8 + dd) * 2]);
            fma2(acc[dd][0],     w2v.x, a2.x);
            fma2(acc[dd][1],     w2v.x, a2.y);
            fma2(acc[dd + 1][0], w2v.y, a2.x);
            fma2(acc[dd + 1][1], w2v.y, a2.y);
        }
    }
    // h1 -> Hs with relu
#pragma unroll
    for (int dd = 0; dd < 8; dd++) {
        const float2 p0 = unpack2(acc[dd][0]), p1 = unpack2(acc[dd][1]);
        float4 o = { fmaxf(p0.x, 0.f), fmaxf(p0.y, 0.f), fmaxf(p1.x, 0.f), fmaxf(p1.y, 0.f) };
        *reinterpret_cast<float4*>(&Hs[(ty * 8 + dd) * 128 + tx * 4]) = o;
    }
    __syncthreads();   // Hs visible; Xs reads done -> safe to reuse Xs for W2 tiles

    // Layer 2: K=64 in 4 tiles of 16 (W2 tile duplicated into Xs region)
    u64 acc2[8][2];
#pragma unroll
    for (int dd = 0; dd < 8; dd++) {
        const float bv = b2[ty * 8 + dd];
        acc2[dd][0] = acc2[dd][1] = pack2(bv, bv);
    }
    for (int kc = 0; kc < 64; kc += 16) {
#pragma unroll
        for (int t = tid; t < 16 * 64; t += 256) {
            const int r = t >> 6, d = t & 63;
            const float w = w2[(kc + r) * 64 + d];
            Xs[r * 128 + 2 * d] = w; Xs[r * 128 + 2 * d + 1] = w;
        }
        __syncthreads();
#pragma unroll
        for (int k = 0; k < 16; k++) {
            const ulonglong2 a2 = *reinterpret_cast<const ulonglong2*>(&Hs[(kc + k) * 128 + tx * 4]);
#pragma unroll
            for (int dd = 0; dd < 8; dd += 2) {
                const ulonglong2 w2v = *reinterpret_cast<const ulonglong2*>(&Xs[k * 128 + (ty * 8 + dd) * 2]);
                fma2(acc2[dd][0],     w2v.x, a2.x);
                fma2(acc2[dd][1],     w2v.x, a2.y);
                fma2(acc2[dd + 1][0], w2v.y, a2.x);
                fma2(acc2[dd + 1][1], w2v.y, a2.y);
            }
        }
        __syncthreads();
    }

    float* ob = out + (size_t)b * 64 * N_ + n0 + tx * 4;
#pragma unroll
    for (int dd = 0; dd < 8; dd++) {
        const float2 p0 = unpack2(acc2[dd][0]), p1 = unpack2(acc2[dd][1]);
        float4 o = { fmaxf(p0.x, 0.f), fmaxf(p0.y, 0.f), fmaxf(p1.x, 0.f), fmaxf(p1.y, 0.f) };
        *reinterpret_cast<float4*>(ob + (size_t)(ty * 8 + dd) * N_) = o;
    }
}

// ---------------------------------------------------------------------------
// GCN layer: out[b][d][n] = relu( sum_k stencil(in[b][k])[n] * Wt[k][d] + s_n*bias[d] )
// D = 128. Stencil computed in-kernel from a zero-padded smem window.
// MEAN: skip output store; write per-block partial sums of relu'd outputs.
// ---------------------------------------------------------------------------
template <int K, bool MEAN>
__global__ void __launch_bounds__(256)
gcn_kernel(const float* __restrict__ in, const float* __restrict__ Wt,
           const float* __restrict__ bias, float* __restrict__ out,
           float* __restrict__ part)
{
    __shared__ __align__(16) float Ls[16 * 256];   // halo window [n0-64, n0+192)
    __shared__ __align__(16) float As[16 * 128];   // stencil result
    __shared__ __align__(16) float Wd[16 * 256];   // weights duplicated {w,w}

    const int tid = threadIdx.x, tx = tid & 31, ty = tid >> 5;
    const int m0 = blockIdx.x * 128;
    const int b  = m0 >> 12, n0 = m0 & (N_ - 1);
    const float* inb = in + (size_t)b * K * N_;

    u64 acc[16][2];
#pragma unroll
    for (int dd = 0; dd < 16; dd++) acc[dd][0] = acc[dd][1] = 0ull;

    for (int kc = 0; kc < K; kc += 16) {
        // 1) Stage window: 16 rows x 256 floats, zero-padded at array ends.
#pragma unroll
        for (int i = 0; i < 4; i++) {
            const int idx = i * 256 + tid;         // 0..1023
            const int r = idx >> 6, c4 = idx & 63;
            const int nw = n0 - 64 + c4 * 4;
            float4 v = make_float4(0.f, 0.f, 0.f, 0.f);
            if (nw >= 0 && nw < N_)
                v = *reinterpret_cast<const float4*>(inb + (size_t)(kc + r) * N_ + nw);
            *reinterpret_cast<float4*>(&Ls[r * 256 + c4 * 4]) = v;
        }
        // Weights duplicated: 16x128 entries, 8 per thread
#pragma unroll
        for (int t = 0; t < 8; t++) {
            const int e = t * 256 + tid;
            const int r = e >> 7, d = e & 127;
            const float w = Wt[(kc + r) * 128 + d];
            Wd[r * 256 + 2 * d] = w; Wd[r * 256 + 2 * d + 1] = w;
        }
        __syncthreads();

        // 2) Stencil: 512 float4 groups, 2 per thread
#pragma unroll
        for (int i = 0; i < 2; i++) {
            const int g  = i * 256 + tid;          // 0..511
            const int r  = g >> 5;
            const int j0 = (g & 31) * 4;
            const float* L = &Ls[r * 256];
            const float4 up = *reinterpret_cast<const float4*>(L + j0);         // n-64
            const float4 dn = *reinterpret_cast<const float4*>(L + j0 + 128);   // n+64
            const float4 c  = *reinterpret_cast<const float4*>(L + j0 + 64);    // n
            const float lm = L[j0 + 63];                                         // left of j0
            const float rp = L[j0 + 68];                                         // right of j0+3
            const int n = n0 + j0;
            const bool lv = (n & 63) != 0;          // left valid (elem 0 only can be col 0)
            const bool rv = ((n + 3) & 63) != 63;   // right valid (elem 3 only can be col 63)
            const int dm = ((n >= 64) ? 1 : 0) + ((n < N_ - 64) ? 1 : 0);
            float4 o;
            o.x = (up.x + dn.x + (lv ? lm : 0.f) + c.y) * recip_deg(dm + (lv ? 1 : 0) + 1);
            o.y = (up.y + dn.y + c.x + c.z)             * recip_deg(dm + 2);
            o.z = (up.z + dn.z + c.y + c.w)             * recip_deg(dm + 2);
            o.w = (up.w + dn.w + c.z + (rv ? rp : 0.f)) * recip_deg(dm + 1 + (rv ? 1 : 0));
            *reinterpret_cast<float4*>(&As[r * 128 + j0]) = o;
        }
        __syncthreads();

        // 3) FFMA2 mainloop: thread d = ty*16+dd, n = n0+tx*4
#pragma unroll
        for (int k = 0; k < 16; k++) {
            const ulonglong2 a2 = *reinterpret_cast<const ulonglong2*>(&As[k * 128 + tx * 4]);
#pragma unroll
            for (int dd = 0; dd < 16; dd += 2) {
                const ulonglong2 w2v = *reinterpret_cast<const ulonglong2*>(&Wd[k * 256 + (ty * 16 + dd) * 2]);
                fma2(acc[dd][0],     w2v.x, a2.x);
                fma2(acc[dd][1],     w2v.x, a2.y);
                fma2(acc[dd + 1][0], w2v.y, a2.x);
                fma2(acc[dd + 1][1], w2v.y, a2.y);
            }
        }
        __syncthreads();
    }

    // Epilogue: scaled bias (+relu); store or mean-partials
    float sc[4];
#pragma unroll
    for (int j = 0; j < 4; j++) {
        const int nn = n0 + tx * 4 + j;
        const int gi = nn >> 6, gj = nn & 63;
        const float fd = (float)((gi > 0) + (gi < 63) + (gj > 0) + (gj < 63));
        sc[j] = fd / (fd + 1e-6f);
    }

    if (!MEAN) {
        float* ob = out + (size_t)b * 128 * N_ + n0 + tx * 4;
#pragma unroll
        for (int dd = 0; dd < 16; dd++) {
            const float bv = __ldg(&bias[ty * 16 + dd]);
            const float2 p0 = unpack2(acc[dd][0]), p1 = unpack2(acc[dd][1]);
            float4 o;
            o.x = fmaxf(fmaf(sc[0], bv, p0.x), 0.f);
            o.y = fmaxf(fmaf(sc[1], bv, p0.y), 0.f);
            o.z = fmaxf(fmaf(sc[2], bv, p1.x), 0.f);
            o.w = fmaxf(fmaf(sc[3], bv, p1.y), 0.f);
            *reinterpret_cast<float4*>(ob + (size_t)(ty * 16 + dd) * N_) = o;
        }
    } else {
        // per-thread sums over 4 n, then warp-reduce over tx (deterministic)
#pragma unroll
        for (int dd = 0; dd < 16; dd++) {
            const float bv = __ldg(&bias[ty * 16 + dd]);
            const float2 p0 = unpack2(acc[dd][0]), p1 = unpack2(acc[dd][1]);
            float s = fmaxf(fmaf(sc[0], bv, p0.x), 0.f)
                    + fmaxf(fmaf(sc[1], bv, p0.y), 0.f)
                    + fmaxf(fmaf(sc[2], bv, p1.x), 0.f)
                    + fmaxf(fmaf(sc[3], bv, p1.y), 0.f);
#pragma unroll
            for (int off = 16; off > 0; off >>= 1)
                s += __shfl_xor_sync(0xffffffffu, s, off);
            if (tx == 0)
                part[(size_t)blockIdx.x * 128 + ty * 16 + dd] = s;  // blockIdx = b*32+blk
        }
    }
}

// ---------------------------------------------------------------------------
// Readout: g[b] = mean partials; out = relu(relu(g r1 + b1) r2 + b2)
// ---------------------------------------------------------------------------
__global__ void __launch_bounds__(256)
readout_kernel(const float* __restrict__ part,
               const float* __restrict__ r1w, const float* __restrict__ r1b,
               const float* __restrict__ r2w, const float* __restrict__ r2b,
               float* __restrict__ out)
{
    __shared__ float gs[128];
    __shared__ float ts[256];
    const int b = blockIdx.x, t = threadIdx.x;

    if (t < 128) {
        float s = 0.f;
        const float* p = part + (size_t)b * 32 * 128 + t;
#pragma unroll
        for (int k = 0; k < 32; k++) s += p[k * 128];
        gs[t] = s * (1.0f / (float)N_);
    }
    __syncthreads();

    float a1 = r1b[t];
#pragma unroll 8
    for (int k = 0; k < 128; k++) a1 = fmaf(gs[k], r1w[k * 256 + t], a1);
    ts[t] = fmaxf(a1, 0.f);
    __syncthreads();

    float a2 = r2b[t];
#pragma unroll 8
    for (int k = 0; k < 256; k++) a2 = fmaf(ts[k], r2w[k * 256 + t], a2);
    out[b * 256 + t] = fmaxf(a2, 0.f);
}

// ---------------------------------------------------------------------------
extern "C" void kernel_launch(void* const* d_in, const int* in_sizes, int n_in,
                              void* d_out, int out_size)
{
    const float* obs  = (const float*)d_in[0];
    const float* e1_w = (const float*)d_in[1];
    const float* e1_b = (const float*)d_in[2];
    const float* e2_w = (const float*)d_in[3];
    const float* e2_b = (const float*)d_in[4];
    const float* g1_w = (const float*)d_in[5];
    const float* g1_b = (const float*)d_in[6];
    const float* g2_w = (const float*)d_in[7];
    const float* g2_b = (const float*)d_in[8];
    const float* g3_w = (const float*)d_in[9];
    const float* g3_b = (const float*)d_in[10];
    const float* r1_w = (const float*)d_in[11];
    const float* r1_b = (const float*)d_in[12];
    const float* r2_w = (const float*)d_in[13];
    const float* r2_b = (const float*)d_in[14];
    float* out = (float*)d_out;

    float *bufA, *bufB, *part;
    cudaGetSymbolAddress((void**)&bufA, g_bufA);
    cudaGetSymbolAddress((void**)&bufB, g_bufB);
    cudaGetSymbolAddress((void**)&part, g_part);

    const int GB = (B_ * N_) / 128;   // 512 blocks

    embed_kernel<<<GB, 256>>>(obs, e1_w, e1_b, e2_w, e2_b, bufB);
    gcn_kernel<64,  false><<<GB, 256>>>(bufB, g1_w, g1_b, bufA, nullptr);
    gcn_kernel<128, false><<<GB, 256>>>(bufA, g2_w, g2_b, bufB, nullptr);
    gcn_kernel<128, true ><<<GB, 256>>>(bufB, g3_w, g3_b, nullptr, part);
    readout_kernel<<<B_, 256>>>(part, r1_w, r1_b, r2_w, r2_b, out);
}

// round 3
// speedup vs baseline: 1.1208x; 1.1196x over previous
#include <cuda_runtime.h>
#include <cuda_bf16.h>
#include <cstdint>

// ---------------------------------------------------------------------------
// GNNRepresentationNetwork  B=16, C=16, N=4096 (64x64), D_E=64, D_H=128, D_R=256
// Feature-major activations [b][d][n].  5 kernels:
//   embed (fused 2-layer MLP), gcn<64>, gcn<128>, gcn<128,MEAN>, readout.
// GCN identity (exact): relu(A(hW+b)) = relu((A h)W + s_n b), s_n = deg/(deg+1e-6)
// Mainloops use fma.rn.f32x2 with per-thread 8n x 8d tiles:
//   smem traffic = 64B per 32 FFMA2 (2 B/FFMA2), weights packed in regs.
// ---------------------------------------------------------------------------

#define B_  16
#define N_  4096

typedef unsigned long long u64;

__device__ float g_bufA[B_ * 128 * N_];
__device__ float g_bufB[B_ * 128 * N_];
__device__ float g_part[B_ * 32 * 128];

__device__ __forceinline__ void fma2(u64& d, u64 a, u64 b) {
    asm("fma.rn.f32x2 %0, %1, %2, %0;" : "+l"(d) : "l"(a), "l"(b));
}
__device__ __forceinline__ u64 pack2(float lo, float hi) {
    u64 r; asm("mov.b64 %0, {%1, %2};" : "=l"(r) : "f"(lo), "f"(hi)); return r;
}
__device__ __forceinline__ float2 unpack2(u64 v) {
    float2 f; asm("mov.b64 {%0, %1}, %2;" : "=f"(f.x), "=f"(f.y) : "l"(v)); return f;
}
__device__ __forceinline__ float recip_deg(int deg) {
    return deg == 4 ? 0.2499999375f : (deg == 3 ? 0.3333332222f : 0.4999997500f);
}

// ---------------------------------------------------------------------------
// Fused embed MLP: out[b][d][n] = relu(relu(x W1 + b1) W2 + b2), D=64
// 256 threads: tx = tid&15 (8 n each), ty = tid>>4 (4 d each)
// ---------------------------------------------------------------------------
__global__ void __launch_bounds__(256)
embed_kernel(const float* __restrict__ obs,
             const float* __restrict__ w1, const float* __restrict__ b1,
             const float* __restrict__ w2, const float* __restrict__ b2,
             float* __restrict__ out)
{
    __shared__ __align__(16) float Xs[16 * 128];   // obs tile / layer-2 A tile src is Hs
    __shared__ __align__(16) float Ws[16 * 64];    // weight k-tile (plain)
    __shared__ __align__(16) float Hs[64 * 128];   // h1

    const int tid = threadIdx.x, tx = tid & 15, ty = tid >> 4;
    const int m0 = blockIdx.x * 128;
    const int b  = m0 >> 12, n0 = m0 & (N_ - 1);
    const float* xb = obs + (size_t)b * 16 * N_ + n0;

    // Stage obs tile: 16 rows x 128 floats = 512 float4, 2 per thread
    {
        const int i0 = tid, i1 = tid + 256;
        *reinterpret_cast<float4*>(&Xs[(i0 >> 5) * 128 + (i0 & 31) * 4]) =
            *(reinterpret_cast<const float4*>(xb + (size_t)(i0 >> 5) * N_) + (i0 & 31));
        *reinterpret_cast<float4*>(&Xs[(i1 >> 5) * 128 + (i1 & 31) * 4]) =
            *(reinterpret_cast<const float4*>(xb + (size_t)(i1 >> 5) * N_) + (i1 & 31));
    }
    // Stage W1 (16x64): 256 float4, 1 per thread
    *reinterpret_cast<float4*>(&Ws[tid * 4]) = *(reinterpret_cast<const float4*>(w1) + tid);
    __syncthreads();

    // Layer 1: acc[4 d][4 n-pairs]
    u64 acc[4][4];
#pragma unroll
    for (int dd = 0; dd < 4; dd++) {
        const float bv = b1[ty * 4 + dd];
        const u64 bp = pack2(bv, bv);
#pragma unroll
        for (int j = 0; j < 4; j++) acc[dd][j] = bp;
    }
#pragma unroll
    for (int k = 0; k < 16; k++) {
        const ulonglong2 a01 = *reinterpret_cast<const ulonglong2*>(&Xs[k * 128 + tx * 8]);
        const ulonglong2 a23 = *reinterpret_cast<const ulonglong2*>(&Xs[k * 128 + tx * 8 + 4]);
        const u64 a[4] = { a01.x, a01.y, a23.x, a23.y };
        const float4 w = *reinterpret_cast<const float4*>(&Ws[k * 64 + ty * 4]);
        const float wv[4] = { w.x, w.y, w.z, w.w };
#pragma unroll
        for (int dd = 0; dd < 4; dd++) {
            const u64 wd = pack2(wv[dd], wv[dd]);
#pragma unroll
            for (int j = 0; j < 4; j++) fma2(acc[dd][j], wd, a[j]);
        }
    }
    // relu -> Hs
#pragma unroll
    for (int dd = 0; dd < 4; dd++) {
        float* hr = &Hs[(ty * 4 + dd) * 128 + tx * 8];
#pragma unroll
        for (int j = 0; j < 4; j += 2) {
            const float2 p0 = unpack2(acc[dd][j]), p1 = unpack2(acc[dd][j + 1]);
            float4 o = { fmaxf(p0.x, 0.f), fmaxf(p0.y, 0.f), fmaxf(p1.x, 0.f), fmaxf(p1.y, 0.f) };
            *reinterpret_cast<float4*>(hr + j * 2) = o;
        }
    }
    __syncthreads();

    // Layer 2: K=64 in 4 tiles of 16
    u64 acc2[4][4];
#pragma unroll
    for (int dd = 0; dd < 4; dd++) {
        const float bv = b2[ty * 4 + dd];
        const u64 bp = pack2(bv, bv);
#pragma unroll
        for (int j = 0; j < 4; j++) acc2[dd][j] = bp;
    }
    for (int kc = 0; kc < 64; kc += 16) {
        __syncthreads();
        *reinterpret_cast<float4*>(&Ws[tid * 4]) =
            *(reinterpret_cast<const float4*>(w2 + kc * 64) + tid);
        __syncthreads();
#pragma unroll
        for (int k = 0; k < 16; k++) {
            const ulonglong2 a01 = *reinterpret_cast<const ulonglong2*>(&Hs[(kc + k) * 128 + tx * 8]);
            const ulonglong2 a23 = *reinterpret_cast<const ulonglong2*>(&Hs[(kc + k) * 128 + tx * 8 + 4]);
            const u64 a[4] = { a01.x, a01.y, a23.x, a23.y };
            const float4 w = *reinterpret_cast<const float4*>(&Ws[k * 64 + ty * 4]);
            const float wv[4] = { w.x, w.y, w.z, w.w };
#pragma unroll
            for (int dd = 0; dd < 4; dd++) {
                const u64 wd = pack2(wv[dd], wv[dd]);
#pragma unroll
                for (int j = 0; j < 4; j++) fma2(acc2[dd][j], wd, a[j]);
            }
        }
    }

    float* ob = out + (size_t)b * 64 * N_ + n0 + tx * 8;
#pragma unroll
    for (int dd = 0; dd < 4; dd++) {
        float* orow = ob + (size_t)(ty * 4 + dd) * N_;
#pragma unroll
        for (int j = 0; j < 4; j += 2) {
            const float2 p0 = unpack2(acc2[dd][j]), p1 = unpack2(acc2[dd][j + 1]);
            float4 o = { fmaxf(p0.x, 0.f), fmaxf(p0.y, 0.f), fmaxf(p1.x, 0.f), fmaxf(p1.y, 0.f) };
            *reinterpret_cast<float4*>(orow + j * 2) = o;
        }
    }
}

// ---------------------------------------------------------------------------
// GCN layer: out[b][d][n] = relu( sum_k stencil(in[b][k])[n] * Wt[k][d] + s_n*bias[d] )
// D = 128. 256 threads: tx = tid&15 (8 n), ty = tid>>4 (8 d).
// MEAN: per-block partial sums instead of store (deterministic).
// ---------------------------------------------------------------------------
template <int K, bool MEAN>
__global__ void __launch_bounds__(256, 2)
gcn_kernel(const float* __restrict__ in, const float* __restrict__ Wt,
           const float* __restrict__ bias, float* __restrict__ out,
           float* __restrict__ part)
{
    __shared__ __align__(16) float Ls[16 * 256];   // halo window [n0-64, n0+192)
    __shared__ __align__(16) float As[16 * 128];   // stencil result
    __shared__ __align__(16) float Ws[16 * 128];   // weight k-tile (plain)

    const int tid = threadIdx.x, tx = tid & 15, ty = tid >> 4;
    const int m0 = blockIdx.x * 128;
    const int b  = m0 >> 12, n0 = m0 & (N_ - 1);
    const float* inb = in + (size_t)b * K * N_;

    u64 acc[8][4];
#pragma unroll
    for (int dd = 0; dd < 8; dd++)
#pragma unroll
        for (int j = 0; j < 4; j++) acc[dd][j] = 0ull;

    for (int kc = 0; kc < K; kc += 16) {
        // 1) Stage halo window: 16 rows x 256 floats (zero-padded ends)
#pragma unroll
        for (int i = 0; i < 4; i++) {
            const int idx = i * 256 + tid;
            const int r = idx >> 6, c4 = idx & 63;
            const int nw = n0 - 64 + c4 * 4;
            float4 v = make_float4(0.f, 0.f, 0.f, 0.f);
            if (nw >= 0 && nw < N_)
                v = *reinterpret_cast<const float4*>(inb + (size_t)(kc + r) * N_ + nw);
            *reinterpret_cast<float4*>(&Ls[r * 256 + c4 * 4]) = v;
        }
        // Stage weights (plain): 16x128 = 512 float4, 2 per thread
        {
            const int i0 = tid, i1 = tid + 256;
            *reinterpret_cast<float4*>(&Ws[i0 * 4]) =
                *(reinterpret_cast<const float4*>(Wt + (size_t)kc * 128) + i0);
            *reinterpret_cast<float4*>(&Ws[i1 * 4]) =
                *(reinterpret_cast<const float4*>(Wt + (size_t)kc * 128) + i1);
        }
        __syncthreads();

        // 2) Stencil: 512 float4 groups, 2 per thread
#pragma unroll
        for (int i = 0; i < 2; i++) {
            const int g  = i * 256 + tid;
            const int r  = g >> 5;
            const int j0 = (g & 31) * 4;
            const float* L = &Ls[r * 256];
            const float4 up = *reinterpret_cast<const float4*>(L + j0);
            const float4 dn = *reinterpret_cast<const float4*>(L + j0 + 128);
            const float4 c  = *reinterpret_cast<const float4*>(L + j0 + 64);
            const float lm = L[j0 + 63];
            const float rp = L[j0 + 68];
            const int n = n0 + j0;
            const bool lv = (n & 63) != 0;
            const bool rv = ((n + 3) & 63) != 63;
            const int dm = ((n >= 64) ? 1 : 0) + ((n < N_ - 64) ? 1 : 0);
            float4 o;
            o.x = (up.x + dn.x + (lv ? lm : 0.f) + c.y) * recip_deg(dm + (lv ? 1 : 0) + 1);
            o.y = (up.y + dn.y + c.x + c.z)             * recip_deg(dm + 2);
            o.z = (up.z + dn.z + c.y + c.w)             * recip_deg(dm + 2);
            o.w = (up.w + dn.w + c.z + (rv ? rp : 0.f)) * recip_deg(dm + 1 + (rv ? 1 : 0));
            *reinterpret_cast<float4*>(&As[r * 128 + j0]) = o;
        }
        __syncthreads();

        // 3) FFMA2 mainloop: 8n x 8d per thread, 64B smem per 32 FFMA2
#pragma unroll
        for (int k = 0; k < 16; k++) {
            const ulonglong2 a01 = *reinterpret_cast<const ulonglong2*>(&As[k * 128 + tx * 8]);
            const ulonglong2 a23 = *reinterpret_cast<const ulonglong2*>(&As[k * 128 + tx * 8 + 4]);
            const u64 a[4] = { a01.x, a01.y, a23.x, a23.y };
            const float4 w0 = *reinterpret_cast<const float4*>(&Ws[k * 128 + ty * 8]);
            const float4 w1 = *reinterpret_cast<const float4*>(&Ws[k * 128 + ty * 8 + 4]);
            const float wv[8] = { w0.x, w0.y, w0.z, w0.w, w1.x, w1.y, w1.z, w1.w };
#pragma unroll
            for (int dd = 0; dd < 8; dd++) {
                const u64 wd = pack2(wv[dd], wv[dd]);
#pragma unroll
                for (int j = 0; j < 4; j++) fma2(acc[dd][j], wd, a[j]);
            }
        }
        __syncthreads();
    }

    // Epilogue: scaled bias + relu
    float sc[8];
#pragma unroll
    for (int j = 0; j < 8; j++) {
        const int nn = n0 + tx * 8 + j;
        const int gi = nn >> 6, gj = nn & 63;
        const float fd = (float)((gi > 0) + (gi < 63) + (gj > 0) + (gj < 63));
        sc[j] = fd / (fd + 1e-6f);
    }

    if (!MEAN) {
        float* ob = out + (size_t)b * 128 * N_ + n0 + tx * 8;
#pragma unroll
        for (int dd = 0; dd < 8; dd++) {
            const float bv = __ldg(&bias[ty * 8 + dd]);
            float* orow = ob + (size_t)(ty * 8 + dd) * N_;
#pragma unroll
            for (int j = 0; j < 4; j += 2) {
                const float2 p0 = unpack2(acc[dd][j]), p1 = unpack2(acc[dd][j + 1]);
                float4 o;
                o.x = fmaxf(fmaf(sc[j * 2 + 0], bv, p0.x), 0.f);
                o.y = fmaxf(fmaf(sc[j * 2 + 1], bv, p0.y), 0.f);
                o.z = fmaxf(fmaf(sc[j * 2 + 2], bv, p1.x), 0.f);
                o.w = fmaxf(fmaf(sc[j * 2 + 3], bv, p1.y), 0.f);
                *reinterpret_cast<float4*>(orow + j * 2) = o;
            }
        }
    } else {
#pragma unroll
        for (int dd = 0; dd < 8; dd++) {
            const float bv = __ldg(&bias[ty * 8 + dd]);
            float s = 0.f;
#pragma unroll
            for (int j = 0; j < 4; j++) {
                const float2 p = unpack2(acc[dd][j]);
                s += fmaxf(fmaf(sc[j * 2 + 0], bv, p.x), 0.f)
                   + fmaxf(fmaf(sc[j * 2 + 1], bv, p.y), 0.f);
            }
            // reduce over tx (16 lanes within each half-warp)
#pragma unroll
            for (int off = 8; off > 0; off >>= 1)
                s += __shfl_xor_sync(0xffffffffu, s, off, 16);
            if (tx == 0)
                part[(size_t)blockIdx.x * 128 + ty * 8 + dd] = s;
        }
    }
}

// ---------------------------------------------------------------------------
// Readout: g[b] = mean partials; out = relu(relu(g r1 + b1) r2 + b2)
// ---------------------------------------------------------------------------
__global__ void __launch_bounds__(256)
readout_kernel(const float* __restrict__ part,
               const float* __restrict__ r1w, const float* __restrict__ r1b,
               const float* __restrict__ r2w, const float* __restrict__ r2b,
               float* __restrict__ out)
{
    __shared__ float gs[128];
    __shared__ float ts[256];
    const int b = blockIdx.x, t = threadIdx.x;

    if (t < 128) {
        float s = 0.f;
        const float* p = part + (size_t)b * 32 * 128 + t;
#pragma unroll
        for (int k = 0; k < 32; k++) s += p[k * 128];
        gs[t] = s * (1.0f / (float)N_);
    }
    __syncthreads();

    float a1 = r1b[t];
#pragma unroll 8
    for (int k = 0; k < 128; k++) a1 = fmaf(gs[k], r1w[k * 256 + t], a1);
    ts[t] = fmaxf(a1, 0.f);
    __syncthreads();

    float a2 = r2b[t];
#pragma unroll 8
    for (int k = 0; k < 256; k++) a2 = fmaf(ts[k], r2w[k * 256 + t], a2);
    out[b * 256 + t] = fmaxf(a2, 0.f);
}

// ---------------------------------------------------------------------------
extern "C" void kernel_launch(void* const* d_in, const int* in_sizes, int n_in,
                              void* d_out, int out_size)
{
    const float* obs  = (const float*)d_in[0];
    const float* e1_w = (const float*)d_in[1];
    const float* e1_b = (const float*)d_in[2];
    const float* e2_w = (const float*)d_in[3];
    const float* e2_b = (const float*)d_in[4];
    const float* g1_w = (const float*)d_in[5];
    const float* g1_b = (const float*)d_in[6];
    const float* g2_w = (const float*)d_in[7];
    const float* g2_b = (const float*)d_in[8];
    const float* g3_w = (const float*)d_in[9];
    const float* g3_b = (const float*)d_in[10];
    const float* r1_w = (const float*)d_in[11];
    const float* r1_b = (const float*)d_in[12];
    const float* r2_w = (const float*)d_in[13];
    const float* r2_b = (const float*)d_in[14];
    float* out = (float*)d_out;

    float *bufA, *bufB, *part;
    cudaGetSymbolAddress((void**)&bufA, g_bufA);
    cudaGetSymbolAddress((void**)&bufB, g_bufB);
    cudaGetSymbolAddress((void**)&part, g_part);

    const int GB = (B_ * N_) / 128;   // 512 blocks

    embed_kernel<<<GB, 256>>>(obs, e1_w, e1_b, e2_w, e2_b, bufB);
    gcn_kernel<64,  false><<<GB, 256>>>(bufB, g1_w, g1_b, bufA, nullptr);
    gcn_kernel<128, false><<<GB, 256>>>(bufA, g2_w, g2_b, bufB, nullptr);
    gcn_kernel<128, true ><<<GB, 256>>>(bufB, g3_w, g3_b, nullptr, part);
    readout_kernel<<<B_, 256>>>(part, r1_w, r1_b, r2_w, r2_b, out);
}